// round 3
// baseline (speedup 1.0000x reference)
#include <cuda_runtime.h>

#define NN   30000
#define KNBR 20
#define D    128
#define K1   384

typedef unsigned long long u64;

__device__ float g_agg[NN * K1];   // 46.08 MB scratch

__device__ __forceinline__ u64 fma2(u64 a, u64 b, u64 c) {
    u64 d;
    asm("fma.rn.f32x2 %0, %1, %2, %3;" : "=l"(d) : "l"(a), "l"(b), "l"(c));
    return d;
}
__device__ __forceinline__ u64 pack2(float x) {
    u64 d;
    unsigned r = __float_as_uint(x);
    asm("mov.b64 %0, {%1, %2};" : "=l"(d) : "r"(r), "r"(r));
    return d;
}
__device__ __forceinline__ void unpack2(u64 v, float& lo, float& hi) {
    unsigned a, b;
    asm("mov.b64 {%0, %1}, %2;" : "=r"(a), "=r"(b) : "l"(v));
    lo = __uint_as_float(a);
    hi = __uint_as_float(b);
}

// cos(x), x in [0, ~1.2e4]: Cody-Waite 3-term reduction mod pi (q < 2^12 so
// q*P1 exact), MUFU.COS on |r|<=pi/2, sign flip by parity of q.
__device__ __forceinline__ float fast_cos(float x) {
    const float MAGIC = 12582912.0f;               // 1.5 * 2^23
    float qm = fmaf(x, 0.31830988618379067f, MAGIC);
    int   iq = __float_as_int(qm);
    float q  = qm - MAGIC;
    float r  = fmaf(q, -3.140625f, x);
    r = fmaf(q, -9.67502593994140625e-4f, r);
    r = fmaf(q, -1.5099579909783764e-7f, r);
    float c = __cosf(r);
    return __int_as_float(__float_as_int(c) ^ (iq << 31));
}

// ============================ Kernel A: aggregation ============================
// Per node n: g_agg[n] = [ sum_k nf[nbr], sum_k cos(dt*w+b), sum_k ef[edge] ]
__global__ void __launch_bounds__(256)
agg_kernel(const float* __restrict__ node_features,
           const float* __restrict__ timestamps,
           const float* __restrict__ edge_features,
           const int*   __restrict__ neighbors,
           const int*   __restrict__ edge_idxs,
           const float* __restrict__ edge_times,
           const float* __restrict__ time_w,
           const float* __restrict__ time_b) {
    const int tid  = threadIdx.x;
    const int lane = tid & 31;
    const int wid  = tid >> 5;
    const float4 tw4 = *(const float4*)(time_w + lane * 4);
    const float4 tb4 = *(const float4*)(time_b + lane * 4);

#pragma unroll
    for (int v = 0; v < 4; ++v) {
        const int n = blockIdx.x * 32 + wid * 4 + v;
        if (n >= NN) continue;
        float4 an = {0.f, 0.f, 0.f, 0.f};
        float4 at = {0.f, 0.f, 0.f, 0.f};
        float4 ae = {0.f, 0.f, 0.f, 0.f};
        const float tsn  = timestamps[n];
        const int*   nb_p = neighbors  + n * KNBR;
        const int*   ei_p = edge_idxs  + n * KNBR;
        const float* et_p = edge_times + n * KNBR;
#pragma unroll 5
        for (int k = 0; k < KNBR; ++k) {
            const int   nb = nb_p[k];
            const int   ei = ei_p[k];
            const float et = et_p[k];
            const float4 f1 = *(const float4*)(node_features + (size_t)nb * D + lane * 4);
            const float4 f2 = *(const float4*)(edge_features + (size_t)ei * D + lane * 4);
            an.x += f1.x; an.y += f1.y; an.z += f1.z; an.w += f1.w;
            ae.x += f2.x; ae.y += f2.y; ae.z += f2.z; ae.w += f2.w;
            const float dl = tsn - et;
            at.x += fast_cos(fmaf(dl, tw4.x, tb4.x));
            at.y += fast_cos(fmaf(dl, tw4.y, tb4.y));
            at.z += fast_cos(fmaf(dl, tw4.z, tb4.z));
            at.w += fast_cos(fmaf(dl, tw4.w, tb4.w));
        }
        float* row = g_agg + (size_t)n * K1 + lane * 4;
        *(float4*)(row)       = an;
        *(float4*)(row + 128) = at;
        *(float4*)(row + 256) = ae;
    }
}

// ============================ Kernel B: fused GEMMs ============================
#define MT   32
#define ASTR 68
#define HSTR 132
#define AS_OFF 0
#define BS_OFF (MT * ASTR)            // 2176
#define HS_OFF (BS_OFF + 64 * D)      // 10368
#define CB_OFF (HS_OFF + MT * HSTR)   // 14592
#define CV_OFF (CB_OFF + D)           // 14720
#define SMB_FLOATS (CV_OFF + D)       // 14848
#define SMB_BYTES (SMB_FLOATS * 4)    // 59392

// A-slice: As[m][0:64] <- src[(n0+m)*srcstr + koff + k], rows clamped
__device__ __forceinline__ void build_A(float* As, const float* __restrict__ src,
                                        int n0, int srcstr, int koff) {
#pragma unroll
    for (int it = threadIdx.x; it < MT * 16; it += 128) {
        int m = it >> 4, kq = it & 15;
        int n = n0 + m; if (n >= NN) n = 0;
        *(float4*)&As[m * ASTR + kq * 4] =
            *(const float4*)(src + (size_t)n * srcstr + koff + kq * 4);
    }
}
// B-slice: Bs[k][c] <- W[(krow0+k)][c], 64 rows x 128 cols, direct coalesced copy
__device__ __forceinline__ void build_B(float* Bs, const float* __restrict__ W, int krow0) {
#pragma unroll
    for (int it = threadIdx.x; it < 64 * 32; it += 128) {
        int k = it >> 5, c = (it & 31) * 4;
        *(float4*)&Bs[k * D + c] = *(const float4*)(W + (size_t)(krow0 + k) * D + c);
    }
}

// 64-deep MMA: thread owns rows {m0, m0+1} x cols {c4+32j+t : j<4, t<4}
__device__ __forceinline__ void mma_slice(const float* __restrict__ Ap, int astr,
                                          const float* __restrict__ Bs,
                                          int m0, int c4, u64 (&acc)[2][8]) {
#pragma unroll 4
    for (int kk = 0; kk < 64; ++kk) {
        const u64 A0 = pack2(Ap[m0 * astr + kk]);
        const u64 A1 = pack2(Ap[(m0 + 1) * astr + kk]);
        const float* brow = Bs + kk * D + c4;
#pragma unroll
        for (int j = 0; j < 4; ++j) {
            ulonglong2 B = *(const ulonglong2*)(brow + 32 * j);
            acc[0][2*j]     = fma2(A0, B.x, acc[0][2*j]);
            acc[0][2*j + 1] = fma2(A0, B.y, acc[0][2*j + 1]);
            acc[1][2*j]     = fma2(A1, B.x, acc[1][2*j]);
            acc[1][2*j + 1] = fma2(A1, B.y, acc[1][2*j + 1]);
        }
    }
}

__global__ void __launch_bounds__(128)
gemm_kernel(const float* __restrict__ nf,
            const float* __restrict__ W1,
            const float* __restrict__ b1,
            const float* __restrict__ W2,
            const float* __restrict__ b2,
            const float* __restrict__ time_b,
            float* __restrict__ out) {
    extern __shared__ float sm[];
    float* As = sm + AS_OFF;
    float* Bs = sm + BS_OFF;
    float* Hs = sm + HS_OFF;
    float* cb = sm + CB_OFF;
    float* cv = sm + CV_OFF;

    const int tid = threadIdx.x;
    const int n0  = blockIdx.x * MT;
    const int m0  = (tid >> 3) * 2;   // 2 rows
    const int c4  = (tid & 7) * 4;    // 4 cols x 4 chunks (stride 32)

    // cvec[c] = b2[c] + sum_d cos(time_b[d]) * W2[256+d][c]
    cb[tid] = cosf(time_b[tid]);
    __syncthreads();
    {
        float a = b2[tid];
#pragma unroll 8
        for (int d = 0; d < D; ++d)
            a = fmaf(cb[d], W2[(size_t)(2 * D + d) * D + tid], a);
        cv[tid] = a;
    }

    // ---------------- GEMM1: acc = agg @ W1 ----------------
    u64 acc[2][8];
#pragma unroll
    for (int i = 0; i < 2; ++i)
#pragma unroll
        for (int j = 0; j < 8; ++j) acc[i][j] = 0ull;

#pragma unroll 1
    for (int s = 0; s < 6; ++s) {
        __syncthreads();
        build_A(As, g_agg, n0, K1, s * 64);
        build_B(Bs, W1, s * 64);
        __syncthreads();
        mma_slice(As, ASTR, Bs, m0, c4, acc);
    }

    // Epilogue 1: H = relu(acc + K*b1) -> Hs[m][c]
#pragma unroll
    for (int i = 0; i < 2; ++i)
#pragma unroll
        for (int j = 0; j < 4; ++j) {
            const int c = c4 + 32 * j;
            float4 bb = *(const float4*)(b1 + c);
            float4 h;
            unpack2(acc[i][2*j],     h.x, h.y);
            unpack2(acc[i][2*j + 1], h.z, h.w);
            h.x = fmaxf(fmaf((float)KNBR, bb.x, h.x), 0.f);
            h.y = fmaxf(fmaf((float)KNBR, bb.y, h.y), 0.f);
            h.z = fmaxf(fmaf((float)KNBR, bb.z, h.z), 0.f);
            h.w = fmaxf(fmaf((float)KNBR, bb.w, h.w), 0.f);
            *(float4*)&Hs[(m0 + i) * HSTR + c] = h;
        }

    // ---------------- GEMM2: out = H @ W2[0:128] + nf @ W2[128:256] + cvec ----
#pragma unroll
    for (int j = 0; j < 4; ++j) {
        const u64 p0 = *(const u64*)&cv[c4 + 32 * j];
        const u64 p1 = *(const u64*)&cv[c4 + 32 * j + 2];
        acc[0][2*j] = p0; acc[0][2*j + 1] = p1;
        acc[1][2*j] = p0; acc[1][2*j + 1] = p1;
    }

#pragma unroll 1
    for (int s = 0; s < 2; ++s) {           // H part (A already in smem)
        __syncthreads();
        build_B(Bs, W2, s * 64);
        __syncthreads();
        mma_slice(Hs + s * 64, HSTR, Bs, m0, c4, acc);
    }
#pragma unroll 1
    for (int s = 0; s < 2; ++s) {           // node-features part
        __syncthreads();
        build_A(As, nf, n0, D, s * 64);
        build_B(Bs, W2, 128 + s * 64);
        __syncthreads();
        mma_slice(As, ASTR, Bs, m0, c4, acc);
    }

#pragma unroll
    for (int i = 0; i < 2; ++i) {
        const int n = n0 + m0 + i;
        if (n < NN) {
#pragma unroll
            for (int j = 0; j < 4; ++j) {
                float4 o;
                unpack2(acc[i][2*j],     o.x, o.y);
                unpack2(acc[i][2*j + 1], o.z, o.w);
                *(float4*)(out + (size_t)n * D + c4 + 32 * j) = o;
            }
        }
    }
}

extern "C" void kernel_launch(void* const* d_in, const int* in_sizes, int n_in,
                              void* d_out, int out_size) {
    const float* node_features = (const float*)d_in[0];
    const float* timestamps    = (const float*)d_in[1];
    const float* edge_features = (const float*)d_in[2];
    const int*   neighbors     = (const int*)d_in[3];
    const int*   edge_idxs     = (const int*)d_in[4];
    const float* edge_times    = (const float*)d_in[5];
    const float* time_w        = (const float*)d_in[6];
    const float* time_b        = (const float*)d_in[7];
    const float* W1            = (const float*)d_in[8];
    const float* b1            = (const float*)d_in[9];
    const float* W2            = (const float*)d_in[10];
    const float* b2            = (const float*)d_in[11];
    float* out = (float*)d_out;

    cudaFuncSetAttribute(gemm_kernel, cudaFuncAttributeMaxDynamicSharedMemorySize, SMB_BYTES);

    const int gridA = (NN + 31) / 32;
    agg_kernel<<<gridA, 256>>>(node_features, timestamps, edge_features,
                               neighbors, edge_idxs, edge_times, time_w, time_b);

    const int gridB = (NN + MT - 1) / MT;
    gemm_kernel<<<gridB, 128, SMB_BYTES>>>(node_features, W1, b1, W2, b2, time_b, out);
}

// round 4
// speedup vs baseline: 2.0130x; 2.0130x over previous
#include <cuda_runtime.h>

#define N_NODES 30000
#define KNBR    20
#define DIM     128
#define M_TILE  32
#define NTHREADS 256
#define AGG_STRIDE 388     // pad 4: rows 8 apart land on distinct bank groups
#define KK_TILE 32

// smem layout (floats)
#define SM_WS    (M_TILE * AGG_STRIDE)       // 12416
#define SM_COSTB (SM_WS + KK_TILE * DIM)     // +4096
#define SM_CVEC  (SM_COSTB + DIM)
#define SMEM_FLOATS (SM_CVEC + DIM)          // 16768
#define SMEM_BYTES (SMEM_FLOATS * 4)         // 67072 -> 3 CTAs/SM

typedef unsigned long long u64;

__device__ __forceinline__ u64 fma2(u64 a, u64 b, u64 c) {
    u64 d;
    asm("fma.rn.f32x2 %0, %1, %2, %3;" : "=l"(d) : "l"(a), "l"(b), "l"(c));
    return d;
}
__device__ __forceinline__ u64 pack2(float x) {
    u64 d;
    unsigned r = __float_as_uint(x);
    asm("mov.b64 %0, {%1, %2};" : "=l"(d) : "r"(r), "r"(r));
    return d;
}
__device__ __forceinline__ void unpack2(u64 v, float& lo, float& hi) {
    unsigned a, b;
    asm("mov.b64 {%0, %1}, %2;" : "=r"(a), "=r"(b) : "l"(v));
    lo = __uint_as_float(a);
    hi = __uint_as_float(b);
}

// cos(x), x in [0, ~1.2e4]: Cody-Waite 3-term reduction mod pi (q < 2^12 so
// q*P1 exact), MUFU.COS on |r|<=pi/2, sign flip by parity of q.
__device__ __forceinline__ float fast_cos(float x) {
    const float MAGIC = 12582912.0f;               // 1.5 * 2^23
    float qm = fmaf(x, 0.31830988618379067f, MAGIC);
    int   iq = __float_as_int(qm);
    float q  = qm - MAGIC;
    float r  = fmaf(q, -3.140625f, x);
    r = fmaf(q, -9.67502593994140625e-4f, r);
    r = fmaf(q, -1.5099579909783764e-7f, r);
    float c = __cosf(r);
    return __int_as_float(__float_as_int(c) ^ (iq << 31));
}

// W slice register prefetch: KK_TILE*DIM = 4096 floats = 1024 float4 / 256 thr
__device__ __forceinline__ void ldW(const float* __restrict__ W, int slice, float4 r[4]) {
    const float4* p = (const float4*)(W + slice * KK_TILE * DIM);
#pragma unroll
    for (int j = 0; j < 4; ++j) r[j] = p[threadIdx.x + j * NTHREADS];
}
__device__ __forceinline__ void stW(float* Ws, const float4 r[4]) {
    float4* p = (float4*)Ws;
#pragma unroll
    for (int j = 0; j < 4; ++j) p[threadIdx.x + j * NTHREADS] = r[j];
}

#define FMA2x2(aa, bu)                          \
    acc[i][0] = fma2(aa, (bu).x, acc[i][0]);    \
    acc[i][1] = fma2(aa, (bu).y, acc[i][1]);

// 32-deep slice: thread owns rows {r8+8i} and cols [coff, coff+4)
__device__ __forceinline__ void gemm_slice(const float* __restrict__ aS,
                                           const float* __restrict__ Ws,
                                           int r8, int coff,
                                           u64 (&acc)[4][2]) {
#pragma unroll
    for (int kk4 = 0; kk4 < KK_TILE / 4; ++kk4) {
        float a4[4][4];
#pragma unroll
        for (int i = 0; i < 4; ++i)
            *(float4*)a4[i] = *(const float4*)&aS[(r8 + 8 * i) * AGG_STRIDE + kk4 * 4];
        ulonglong2 bv[4];
#pragma unroll
        for (int k = 0; k < 4; ++k)
            bv[k] = *(const ulonglong2*)&Ws[(kk4 * 4 + k) * DIM + coff];
#pragma unroll
        for (int k = 0; k < 4; ++k)
#pragma unroll
            for (int i = 0; i < 4; ++i) {
                u64 aa = pack2(a4[i][k]);
                FMA2x2(aa, bv[k]);
            }
    }
}

__global__ void __launch_bounds__(NTHREADS, 3)
tgs_kernel(const float* __restrict__ node_features,
           const float* __restrict__ timestamps,
           const float* __restrict__ edge_features,
           const int*   __restrict__ neighbors,
           const int*   __restrict__ edge_idxs,
           const float* __restrict__ edge_times,
           const float* __restrict__ time_w,
           const float* __restrict__ time_b,
           const float* __restrict__ W1,
           const float* __restrict__ b1,
           const float* __restrict__ W2,
           const float* __restrict__ b2,
           float* __restrict__ out) {
    extern __shared__ float smem[];
    float* aggS = smem;                 // [M_TILE][AGG_STRIDE]
    float* Ws   = smem + SM_WS;         // [KK_TILE][DIM]

    const int tid  = threadIdx.x;
    const int lane = tid & 31;
    const int wid  = tid >> 5;
    const int blk  = blockIdx.x;

    if (tid < DIM) smem[SM_COSTB + tid] = cosf(time_b[tid]);

    // ---------------- Phase 1: per-node aggregation (sum over K) ----------------
    {
        const float4 tw4 = *(const float4*)(time_w + lane * 4);
        const float4 tb4 = *(const float4*)(time_b + lane * 4);
#pragma unroll
        for (int v = 0; v < 4; ++v) {
            const int m = wid * 4 + v;
            const int n = blk * M_TILE + m;
            float4 an = {0.f, 0.f, 0.f, 0.f};
            float4 at = {0.f, 0.f, 0.f, 0.f};
            float4 ae = {0.f, 0.f, 0.f, 0.f};
            if (n < N_NODES) {
                const float tsn  = timestamps[n];
                const int*   nb_p = neighbors  + n * KNBR;
                const int*   ei_p = edge_idxs  + n * KNBR;
                const float* et_p = edge_times + n * KNBR;
#pragma unroll 10
                for (int k = 0; k < KNBR; ++k) {
                    const int   nb = nb_p[k];
                    const int   ei = ei_p[k];
                    const float et = et_p[k];
                    const float4 f1 = *(const float4*)(node_features + (size_t)nb * DIM + lane * 4);
                    const float4 f2 = *(const float4*)(edge_features + (size_t)ei * DIM + lane * 4);
                    an.x += f1.x; an.y += f1.y; an.z += f1.z; an.w += f1.w;
                    ae.x += f2.x; ae.y += f2.y; ae.z += f2.z; ae.w += f2.w;
                    const float dl = tsn - et;
                    at.x += fast_cos(fmaf(dl, tw4.x, tb4.x));
                    at.y += fast_cos(fmaf(dl, tw4.y, tb4.y));
                    at.z += fast_cos(fmaf(dl, tw4.z, tb4.z));
                    at.w += fast_cos(fmaf(dl, tw4.w, tb4.w));
                }
            }
            float* row = aggS + m * AGG_STRIDE + lane * 4;
            *(float4*)(row)       = an;   // cols [0,128)
            *(float4*)(row + 128) = at;   // cols [128,256)
            *(float4*)(row + 256) = ae;   // cols [256,384)
        }
    }

    const int r8   = lane >> 2;           // rows r8 + 8i
    const int c2   = lane & 3;
    const int coff = wid * 16 + c2 * 4;   // 4 output columns

    float4 wreg[4];
    ldW(W1, 0, wreg);
    __syncthreads();   // aggS + costb ready

    // cvec[c] = b2[c] + sum_d cos(time_b[d]) * W2[256+d][c]  (per-CTA, cheap)
    if (tid < DIM) {
        float a = b2[tid];
#pragma unroll 16
        for (int d = 0; d < DIM; ++d)
            a = fmaf(smem[SM_COSTB + d], W2[(size_t)(2 * DIM + d) * DIM + tid], a);
        smem[SM_CVEC + tid] = a;
    }

    // ---------------- GEMM1: H = relu(agg @ W1 + K*b1) ----------------
    u64 acc[4][2];
#pragma unroll
    for (int i = 0; i < 4; ++i) { acc[i][0] = 0ull; acc[i][1] = 0ull; }

#pragma unroll 1
    for (int t = 0; t < 384 / KK_TILE; ++t) {
        stW(Ws, wreg);
        if (t < 384 / KK_TILE - 1) ldW(W1, t + 1, wreg);
        __syncthreads();
        gemm_slice(aggS + t * KK_TILE, Ws, r8, coff, acc);
        __syncthreads();
    }

    ldW(W2, 0, wreg);   // prefetch W2 slice 0 during epilogue

    // Epilogue 1: H -> aggS cols [0,128)
    {
        const float4 b1v = *(const float4*)&b1[coff];
#pragma unroll
        for (int i = 0; i < 4; ++i) {
            float4 h;
            unpack2(acc[i][0], h.x, h.y);
            unpack2(acc[i][1], h.z, h.w);
            h.x = fmaxf(fmaf((float)KNBR, b1v.x, h.x), 0.f);
            h.y = fmaxf(fmaf((float)KNBR, b1v.y, h.y), 0.f);
            h.z = fmaxf(fmaf((float)KNBR, b1v.z, h.z), 0.f);
            h.w = fmaxf(fmaf((float)KNBR, b1v.w, h.w), 0.f);
            *(float4*)&aggS[(r8 + 8 * i) * AGG_STRIDE + coff] = h;
        }
    }
    // node_features of this tile -> aggS cols [128,256)
    {
        const int m = tid >> 3;
        const int u = tid & 7;
        const int n = blk * M_TILE + m;
#pragma unroll
        for (int v2 = 0; v2 < 4; ++v2) {
            const int col = u * 16 + v2 * 4;
            float4 val = {0.f, 0.f, 0.f, 0.f};
            if (n < N_NODES) val = *(const float4*)(node_features + (size_t)n * DIM + col);
            *(float4*)&aggS[m * AGG_STRIDE + 128 + col] = val;
        }
    }
    __syncthreads();

    // ---------------- GEMM2: out = [H | nf] @ W2[0:256] + cvec ----------------
    {
        const u64 cv0 = *(const u64*)&smem[SM_CVEC + coff];
        const u64 cv1 = *(const u64*)&smem[SM_CVEC + coff + 2];
#pragma unroll
        for (int i = 0; i < 4; ++i) { acc[i][0] = cv0; acc[i][1] = cv1; }
    }
#pragma unroll 1
    for (int t = 0; t < 256 / KK_TILE; ++t) {
        stW(Ws, wreg);
        if (t < 256 / KK_TILE - 1) ldW(W2, t + 1, wreg);
        __syncthreads();
        gemm_slice(aggS + t * KK_TILE, Ws, r8, coff, acc);
        __syncthreads();
    }

#pragma unroll
    for (int i = 0; i < 4; ++i) {
        const int n = blk * M_TILE + r8 + 8 * i;
        if (n < N_NODES) {
            float4 o;
            unpack2(acc[i][0], o.x, o.y);
            unpack2(acc[i][1], o.z, o.w);
            *(float4*)(out + (size_t)n * DIM + coff) = o;
        }
    }
}

extern "C" void kernel_launch(void* const* d_in, const int* in_sizes, int n_in,
                              void* d_out, int out_size) {
    const float* node_features = (const float*)d_in[0];
    const float* timestamps    = (const float*)d_in[1];
    const float* edge_features = (const float*)d_in[2];
    const int*   neighbors     = (const int*)d_in[3];
    const int*   edge_idxs     = (const int*)d_in[4];
    const float* edge_times    = (const float*)d_in[5];
    const float* time_w        = (const float*)d_in[6];
    const float* time_b        = (const float*)d_in[7];
    const float* W1            = (const float*)d_in[8];
    const float* b1            = (const float*)d_in[9];
    const float* W2            = (const float*)d_in[10];
    const float* b2            = (const float*)d_in[11];
    float* out = (float*)d_out;

    cudaFuncSetAttribute(tgs_kernel, cudaFuncAttributeMaxDynamicSharedMemorySize, SMEM_BYTES);

    const int grid = (N_NODES + M_TILE - 1) / M_TILE;
    tgs_kernel<<<grid, NTHREADS, SMEM_BYTES>>>(
        node_features, timestamps, edge_features, neighbors, edge_idxs,
        edge_times, time_w, time_b, W1, b1, W2, b2, out);
}